// round 1
// baseline (speedup 1.0000x reference)
#include <cuda_runtime.h>
#include <cuda_bf16.h>

#define Bb 4
#define Hh 16
#define Ll 8192
#define Dd 64
#define BH (Bb*Hh)
#define SCALE 0.10511205190671431f   // 8192^(-1/4)

#define NCHUNK 32
#define ROWS_PER_CHUNK (Ll / NCHUNK)   // 256
#define TILE_ROWS 16
#define QROWS 64

// Scratch (allocation-free rule: __device__ globals)
__device__ float g_scratch[(size_t)NCHUNK * BH * Dd * Dd];  // 33.5 MB partial KV
__device__ float g_KV[(size_t)BH * Dd * Dd];                // 1 MB final KV

// ---- packed f32x2 helpers (FFMA2 path; only reachable via PTX) ----
__device__ __forceinline__ unsigned long long pack2(float a, float b) {
    unsigned long long r;
    asm("mov.b64 %0, {%1, %2};" : "=l"(r) : "f"(a), "f"(b));
    return r;
}
__device__ __forceinline__ unsigned long long fma2(unsigned long long a,
                                                   unsigned long long b,
                                                   unsigned long long c) {
    unsigned long long d;
    asm("fma.rn.f32x2 %0, %1, %2, %3;" : "=l"(d) : "l"(a), "l"(b), "l"(c));
    return d;
}

__device__ __forceinline__ float elu_p1(float x) {
    // elu(x)+1 = x+1 (x>0) else exp(x)
    float e = __expf(x);
    return x > 0.0f ? x + 1.0f : e;
}

// ============================================================
// Phase 1: partial KV[d][e] = sum_l Kf[l][d] * Vm[l][e]
// grid: (NCHUNK, BH), block: 64 threads, 8x8 tile per thread
// ============================================================
__global__ void __launch_bounds__(64, 8)
phase1_kernel(const float* __restrict__ Kp, const float* __restrict__ Vp,
              const float* __restrict__ maskp, const float* __restrict__ pip,
              const float* __restrict__ mup) {
    __shared__ float kfs[TILE_ROWS][Dd];
    __shared__ float vsm[TILE_ROWS][Dd];
    __shared__ float mueff[Dd];

    const int chunk = blockIdx.x;
    const int bh    = blockIdx.y;
    const int b     = bh / Hh;
    const int h     = bh % Hh;
    const int t     = threadIdx.x;

    const float p0 = fminf(fmaxf(pip[0], 0.0f), 1.0f);
    const float p1 = fminf(fmaxf(pip[1], 0.0f), 1.0f);
    const float psum = p0 + p1;
    mueff[t] = p0 * mup[h * Dd + t] + p1 * mup[(Hh + h) * Dd + t];
    __syncthreads();

    const int dr = (t >> 3) * 8;
    const int er = (t & 7) * 8;

    const size_t base = ((size_t)bh * Ll + (size_t)chunk * ROWS_PER_CHUNK) * Dd;
    const float* __restrict__ Kbase = Kp + base;
    const float* __restrict__ Vbase = Vp + base;
    const float* __restrict__ mbase = maskp + (size_t)b * Ll + (size_t)chunk * ROWS_PER_CHUNK;

    unsigned long long acc[8][4];
#pragma unroll
    for (int i = 0; i < 8; i++)
#pragma unroll
        for (int j = 0; j < 4; j++) acc[i][j] = 0ULL;

    for (int r0 = 0; r0 < ROWS_PER_CHUNK; r0 += TILE_ROWS) {
        __syncthreads();
        // Load 16x64 K and V; fuse feature map on K and mask on V.
#pragma unroll
        for (int j = 0; j < 4; j++) {
            const int f4  = t + 64 * j;        // 0..255 float4s
            const int row = f4 >> 4;
            const int db  = (f4 & 15) * 4;
            const size_t off = (size_t)(r0 + row) * Dd + db;
            float4 kq = *reinterpret_cast<const float4*>(Kbase + off);
            float4 vq = *reinterpret_cast<const float4*>(Vbase + off);
            const float m  = mbase[r0 + row];
            const float ms = m * SCALE;
            kq.x = elu_p1(kq.x * psum - mueff[db + 0]) * ms;
            kq.y = elu_p1(kq.y * psum - mueff[db + 1]) * ms;
            kq.z = elu_p1(kq.z * psum - mueff[db + 2]) * ms;
            kq.w = elu_p1(kq.w * psum - mueff[db + 3]) * ms;
            vq.x *= m; vq.y *= m; vq.z *= m; vq.w *= m;
            *reinterpret_cast<float4*>(&kfs[row][db]) = kq;
            *reinterpret_cast<float4*>(&vsm[row][db]) = vq;
        }
        __syncthreads();

#pragma unroll 4
        for (int r = 0; r < TILE_ROWS; r++) {
            const float4 ka = *reinterpret_cast<const float4*>(&kfs[r][dr]);
            const float4 kb = *reinterpret_cast<const float4*>(&kfs[r][dr + 4]);
            const ulonglong2 v01 = *reinterpret_cast<const ulonglong2*>(&vsm[r][er]);
            const ulonglong2 v23 = *reinterpret_cast<const ulonglong2*>(&vsm[r][er + 4]);
            const unsigned long long bb[4] = {v01.x, v01.y, v23.x, v23.y};
            const float kk[8] = {ka.x, ka.y, ka.z, ka.w, kb.x, kb.y, kb.z, kb.w};
#pragma unroll
            for (int i = 0; i < 8; i++) {
                const unsigned long long a2 = pack2(kk[i], kk[i]);
#pragma unroll
                for (int j = 0; j < 4; j++)
                    acc[i][j] = fma2(a2, bb[j], acc[i][j]);
            }
        }
    }

    float* outp = g_scratch + ((size_t)chunk * BH + bh) * (Dd * Dd);
#pragma unroll
    for (int i = 0; i < 8; i++) {
        ulonglong2 w0 = {acc[i][0], acc[i][1]};
        ulonglong2 w1 = {acc[i][2], acc[i][3]};
        *reinterpret_cast<ulonglong2*>(&outp[(dr + i) * Dd + er + 0]) = w0;
        *reinterpret_cast<ulonglong2*>(&outp[(dr + i) * Dd + er + 4]) = w1;
    }
}

// ============================================================
// Reduce: sum partials over NCHUNK. grid (BH, 8), 128 threads
// ============================================================
__global__ void __launch_bounds__(128)
reduce_kernel() {
    const int bh   = blockIdx.x;
    const int part = blockIdx.y;
    const int t    = threadIdx.x;
    const int entry = part * 512 + t * 4;
    float4 s = make_float4(0.f, 0.f, 0.f, 0.f);
#pragma unroll
    for (int c = 0; c < NCHUNK; c++) {
        const float4 v = *reinterpret_cast<const float4*>(
            g_scratch + ((size_t)c * BH + bh) * (Dd * Dd) + entry);
        s.x += v.x; s.y += v.y; s.z += v.z; s.w += v.w;
    }
    *reinterpret_cast<float4*>(g_KV + (size_t)bh * (Dd * Dd) + entry) = s;
}

// ============================================================
// Phase 2: out[l][e] = sum_d Qf[l][d] * KV[d][e]
// grid: (L/QROWS, BH), block: 64 threads, 8x8 tile per thread
// ============================================================
__global__ void __launch_bounds__(64, 6)
phase2_kernel(const float* __restrict__ Qp, float* __restrict__ outp) {
    __shared__ float Qs[QROWS][Dd + 1];   // stride 65: conflict-free column reads
    __shared__ float KVs[Dd][Dd];

    const int rb = blockIdx.x;
    const int bh = blockIdx.y;
    const int t  = threadIdx.x;
    const int er = (t & 7) * 8;
    const int rg = (t >> 3) * 8;

    // Load KV tile (16 KB)
    {
        const float4* kvp = reinterpret_cast<const float4*>(g_KV + (size_t)bh * Dd * Dd);
        float4* kvs4 = reinterpret_cast<float4*>(&KVs[0][0]);
#pragma unroll
        for (int j = 0; j < 16; j++) kvs4[t + 64 * j] = kvp[t + 64 * j];
    }

    // Load + transform Q tile (64 rows)
    const float* __restrict__ Qbase = Qp + ((size_t)bh * Ll + (size_t)rb * QROWS) * Dd;
#pragma unroll
    for (int j = 0; j < 16; j++) {
        const int f4  = t + 64 * j;
        const int row = f4 >> 4;
        const int db  = (f4 & 15) * 4;
        float4 q = *reinterpret_cast<const float4*>(Qbase + (size_t)row * Dd + db);
        q.x = elu_p1(q.x) * SCALE;
        q.y = elu_p1(q.y) * SCALE;
        q.z = elu_p1(q.z) * SCALE;
        q.w = elu_p1(q.w) * SCALE;
        Qs[row][db + 0] = q.x;
        Qs[row][db + 1] = q.y;
        Qs[row][db + 2] = q.z;
        Qs[row][db + 3] = q.w;
    }
    __syncthreads();

    unsigned long long acc[8][4];
#pragma unroll
    for (int i = 0; i < 8; i++)
#pragma unroll
        for (int j = 0; j < 4; j++) acc[i][j] = 0ULL;

#pragma unroll 8
    for (int d = 0; d < Dd; d++) {
        const ulonglong2 v01 = *reinterpret_cast<const ulonglong2*>(&KVs[d][er]);
        const ulonglong2 v23 = *reinterpret_cast<const ulonglong2*>(&KVs[d][er + 4]);
        const unsigned long long bb[4] = {v01.x, v01.y, v23.x, v23.y};
#pragma unroll
        for (int i = 0; i < 8; i++) {
            const float qv = Qs[rg + i][d];
            const unsigned long long a2 = pack2(qv, qv);
#pragma unroll
            for (int j = 0; j < 4; j++)
                acc[i][j] = fma2(a2, bb[j], acc[i][j]);
        }
    }

    float* __restrict__ obase = outp + ((size_t)bh * Ll + (size_t)rb * QROWS) * Dd;
#pragma unroll
    for (int i = 0; i < 8; i++) {
        ulonglong2 w0 = {acc[i][0], acc[i][1]};
        ulonglong2 w1 = {acc[i][2], acc[i][3]};
        *reinterpret_cast<ulonglong2*>(&obase[(size_t)(rg + i) * Dd + er + 0]) = w0;
        *reinterpret_cast<ulonglong2*>(&obase[(size_t)(rg + i) * Dd + er + 4]) = w1;
    }
}

// ============================================================
// Launch
// ============================================================
extern "C" void kernel_launch(void* const* d_in, const int* in_sizes, int n_in,
                              void* d_out, int out_size) {
    const float* Q    = (const float*)d_in[0];
    const float* K    = (const float*)d_in[1];
    const float* V    = (const float*)d_in[2];
    const float* mask = (const float*)d_in[3];
    const float* pi   = (const float*)d_in[4];
    const float* mu   = (const float*)d_in[5];
    float* out = (float*)d_out;

    dim3 g1(NCHUNK, BH);
    phase1_kernel<<<g1, 64>>>(K, V, mask, pi, mu);

    dim3 g2(BH, 8);
    reduce_kernel<<<g2, 128>>>();

    dim3 g3(Ll / QROWS, BH);
    phase2_kernel<<<g3, 64>>>(Q, out);
}

// round 2
// speedup vs baseline: 1.0022x; 1.0022x over previous
#include <cuda_runtime.h>
#include <cuda_bf16.h>

#define Bb 4
#define Hh 16
#define Ll 8192
#define Dd 64
#define BH (Bb*Hh)
#define SCALE 0.10511205190671431f   // 8192^(-1/4)

#define NCHUNK 32
#define ROWS_PER_CHUNK (Ll / NCHUNK)   // 256
#define TILE_ROWS 16
#define QROWS 64

// Scratch (allocation-free rule: __device__ globals)
__device__ float g_scratch[(size_t)NCHUNK * BH * Dd * Dd];  // 33.5 MB partial KV
__device__ float g_KV[(size_t)BH * Dd * Dd];                // 1 MB final KV

// ---- packed f32x2 helpers (FFMA2 path; only reachable via PTX) ----
__device__ __forceinline__ unsigned long long pack2(float a, float b) {
    unsigned long long r;
    asm("mov.b64 %0, {%1, %2};" : "=l"(r) : "f"(a), "f"(b));
    return r;
}
__device__ __forceinline__ unsigned long long fma2(unsigned long long a,
                                                   unsigned long long b,
                                                   unsigned long long c) {
    unsigned long long d;
    asm("fma.rn.f32x2 %0, %1, %2, %3;" : "=l"(d) : "l"(a), "l"(b), "l"(c));
    return d;
}

__device__ __forceinline__ float elu_p1(float x) {
    // elu(x)+1 = x+1 (x>0) else exp(x)
    float e = __expf(x);
    return x > 0.0f ? x + 1.0f : e;
}

// ============================================================
// Phase 1: partial KV[d][e] = sum_l Kf[l][d] * Vm[l][e]
// grid: (NCHUNK, BH), block: 64 threads, 8x8 tile per thread
// ============================================================
__global__ void __launch_bounds__(64, 8)
phase1_kernel(const float* __restrict__ Kp, const float* __restrict__ Vp,
              const float* __restrict__ maskp, const float* __restrict__ pip,
              const float* __restrict__ mup) {
    __shared__ float kfs[TILE_ROWS][Dd];
    __shared__ float vsm[TILE_ROWS][Dd];
    __shared__ float mueff[Dd];

    const int chunk = blockIdx.x;
    const int bh    = blockIdx.y;
    const int b     = bh / Hh;
    const int h     = bh % Hh;
    const int t     = threadIdx.x;

    const float p0 = fminf(fmaxf(pip[0], 0.0f), 1.0f);
    const float p1 = fminf(fmaxf(pip[1], 0.0f), 1.0f);
    const float psum = p0 + p1;
    mueff[t] = p0 * mup[h * Dd + t] + p1 * mup[(Hh + h) * Dd + t];
    __syncthreads();

    const int dr = (t >> 3) * 8;
    const int er = (t & 7) * 8;

    const size_t base = ((size_t)bh * Ll + (size_t)chunk * ROWS_PER_CHUNK) * Dd;
    const float* __restrict__ Kbase = Kp + base;
    const float* __restrict__ Vbase = Vp + base;
    const float* __restrict__ mbase = maskp + (size_t)b * Ll + (size_t)chunk * ROWS_PER_CHUNK;

    unsigned long long acc[8][4];
#pragma unroll
    for (int i = 0; i < 8; i++)
#pragma unroll
        for (int j = 0; j < 4; j++) acc[i][j] = 0ULL;

    for (int r0 = 0; r0 < ROWS_PER_CHUNK; r0 += TILE_ROWS) {
        __syncthreads();
        // Load 16x64 K and V; fuse feature map on K and mask on V.
#pragma unroll
        for (int j = 0; j < 4; j++) {
            const int f4  = t + 64 * j;        // 0..255 float4s
            const int row = f4 >> 4;
            const int db  = (f4 & 15) * 4;
            const size_t off = (size_t)(r0 + row) * Dd + db;
            float4 kq = *reinterpret_cast<const float4*>(Kbase + off);
            float4 vq = *reinterpret_cast<const float4*>(Vbase + off);
            const float m  = mbase[r0 + row];
            const float ms = m * SCALE;
            kq.x = elu_p1(kq.x * psum - mueff[db + 0]) * ms;
            kq.y = elu_p1(kq.y * psum - mueff[db + 1]) * ms;
            kq.z = elu_p1(kq.z * psum - mueff[db + 2]) * ms;
            kq.w = elu_p1(kq.w * psum - mueff[db + 3]) * ms;
            vq.x *= m; vq.y *= m; vq.z *= m; vq.w *= m;
            *reinterpret_cast<float4*>(&kfs[row][db]) = kq;
            *reinterpret_cast<float4*>(&vsm[row][db]) = vq;
        }
        __syncthreads();

#pragma unroll 4
        for (int r = 0; r < TILE_ROWS; r++) {
            const float4 ka = *reinterpret_cast<const float4*>(&kfs[r][dr]);
            const float4 kb = *reinterpret_cast<const float4*>(&kfs[r][dr + 4]);
            const ulonglong2 v01 = *reinterpret_cast<const ulonglong2*>(&vsm[r][er]);
            const ulonglong2 v23 = *reinterpret_cast<const ulonglong2*>(&vsm[r][er + 4]);
            const unsigned long long bb[4] = {v01.x, v01.y, v23.x, v23.y};
            const float kk[8] = {ka.x, ka.y, ka.z, ka.w, kb.x, kb.y, kb.z, kb.w};
#pragma unroll
            for (int i = 0; i < 8; i++) {
                const unsigned long long a2 = pack2(kk[i], kk[i]);
#pragma unroll
                for (int j = 0; j < 4; j++)
                    acc[i][j] = fma2(a2, bb[j], acc[i][j]);
            }
        }
    }

    float* outp = g_scratch + ((size_t)chunk * BH + bh) * (Dd * Dd);
#pragma unroll
    for (int i = 0; i < 8; i++) {
        ulonglong2 w0 = {acc[i][0], acc[i][1]};
        ulonglong2 w1 = {acc[i][2], acc[i][3]};
        *reinterpret_cast<ulonglong2*>(&outp[(dr + i) * Dd + er + 0]) = w0;
        *reinterpret_cast<ulonglong2*>(&outp[(dr + i) * Dd + er + 4]) = w1;
    }
}

// ============================================================
// Reduce: sum partials over NCHUNK. grid (BH, 8), 128 threads
// ============================================================
__global__ void __launch_bounds__(128)
reduce_kernel() {
    const int bh   = blockIdx.x;
    const int part = blockIdx.y;
    const int t    = threadIdx.x;
    const int entry = part * 512 + t * 4;
    float4 s = make_float4(0.f, 0.f, 0.f, 0.f);
#pragma unroll
    for (int c = 0; c < NCHUNK; c++) {
        const float4 v = *reinterpret_cast<const float4*>(
            g_scratch + ((size_t)c * BH + bh) * (Dd * Dd) + entry);
        s.x += v.x; s.y += v.y; s.z += v.z; s.w += v.w;
    }
    *reinterpret_cast<float4*>(g_KV + (size_t)bh * (Dd * Dd) + entry) = s;
}

// ============================================================
// Phase 2: out[l][e] = sum_d Qf[l][d] * KV[d][e]
// grid: (L/QROWS, BH), block: 64 threads, 8x8 tile per thread
// ============================================================
__global__ void __launch_bounds__(64, 6)
phase2_kernel(const float* __restrict__ Qp, float* __restrict__ outp) {
    __shared__ float Qs[QROWS][Dd + 1];   // stride 65: conflict-free column reads
    __shared__ float KVs[Dd][Dd];

    const int rb = blockIdx.x;
    const int bh = blockIdx.y;
    const int t  = threadIdx.x;
    const int er = (t & 7) * 8;
    const int rg = (t >> 3) * 8;

    // Load KV tile (16 KB)
    {
        const float4* kvp = reinterpret_cast<const float4*>(g_KV + (size_t)bh * Dd * Dd);
        float4* kvs4 = reinterpret_cast<float4*>(&KVs[0][0]);
#pragma unroll
        for (int j = 0; j < 16; j++) kvs4[t + 64 * j] = kvp[t + 64 * j];
    }

    // Load + transform Q tile (64 rows)
    const float* __restrict__ Qbase = Qp + ((size_t)bh * Ll + (size_t)rb * QROWS) * Dd;
#pragma unroll
    for (int j = 0; j < 16; j++) {
        const int f4  = t + 64 * j;
        const int row = f4 >> 4;
        const int db  = (f4 & 15) * 4;
        float4 q = *reinterpret_cast<const float4*>(Qbase + (size_t)row * Dd + db);
        q.x = elu_p1(q.x) * SCALE;
        q.y = elu_p1(q.y) * SCALE;
        q.z = elu_p1(q.z) * SCALE;
        q.w = elu_p1(q.w) * SCALE;
        Qs[row][db + 0] = q.x;
        Qs[row][db + 1] = q.y;
        Qs[row][db + 2] = q.z;
        Qs[row][db + 3] = q.w;
    }
    __syncthreads();

    unsigned long long acc[8][4];
#pragma unroll
    for (int i = 0; i < 8; i++)
#pragma unroll
        for (int j = 0; j < 4; j++) acc[i][j] = 0ULL;

#pragma unroll 8
    for (int d = 0; d < Dd; d++) {
        const ulonglong2 v01 = *reinterpret_cast<const ulonglong2*>(&KVs[d][er]);
        const ulonglong2 v23 = *reinterpret_cast<const ulonglong2*>(&KVs[d][er + 4]);
        const unsigned long long bb[4] = {v01.x, v01.y, v23.x, v23.y};
#pragma unroll
        for (int i = 0; i < 8; i++) {
            const float qv = Qs[rg + i][d];
            const unsigned long long a2 = pack2(qv, qv);
#pragma unroll
            for (int j = 0; j < 4; j++)
                acc[i][j] = fma2(a2, bb[j], acc[i][j]);
        }
    }

    float* __restrict__ obase = outp + ((size_t)bh * Ll + (size_t)rb * QROWS) * Dd;
#pragma unroll
    for (int i = 0; i < 8; i++) {
        ulonglong2 w0 = {acc[i][0], acc[i][1]};
        ulonglong2 w1 = {acc[i][2], acc[i][3]};
        *reinterpret_cast<ulonglong2*>(&obase[(size_t)(rg + i) * Dd + er + 0]) = w0;
        *reinterpret_cast<ulonglong2*>(&obase[(size_t)(rg + i) * Dd + er + 4]) = w1;
    }
}

// ============================================================
// Launch
// ============================================================
extern "C" void kernel_launch(void* const* d_in, const int* in_sizes, int n_in,
                              void* d_out, int out_size) {
    const float* Q    = (const float*)d_in[0];
    const float* K    = (const float*)d_in[1];
    const float* V    = (const float*)d_in[2];
    const float* mask = (const float*)d_in[3];
    const float* pi   = (const float*)d_in[4];
    const float* mu   = (const float*)d_in[5];
    float* out = (float*)d_out;

    dim3 g1(NCHUNK, BH);
    phase1_kernel<<<g1, 64>>>(K, V, mask, pi, mu);

    dim3 g2(BH, 8);
    reduce_kernel<<<g2, 128>>>();

    dim3 g3(Ll / QROWS, BH);
    phase2_kernel<<<g3, 64>>>(Q, out);
}

// round 4
// speedup vs baseline: 1.3656x; 1.3625x over previous
#include <cuda_runtime.h>
#include <cuda_bf16.h>
#include <cstdint>

#define Bb 4
#define Hh 16
#define Ll 8192
#define Dd 64
#define BH (Bb*Hh)
#define SCALE 0.10511205190671431f   // 8192^(-1/4)
#define NCHUNK 16
#define RPC (Ll/NCHUNK)              // 512 rows per chunk
#define NTILE (RPC/64)               // 8 tiles of 64 rows
#define PAD 72                       // bf16 row stride (144B, 16B-multiple, conflict-free)

// __device__ scratch (allocation-free rule)
__device__ float g_scratch[(size_t)NCHUNK*BH*Dd*Dd];          // 16.7 MB fp32 partial KV
__device__ __nv_bfloat16 g_KVhi[(size_t)BH*Dd*Dd];            // 0.5 MB
__device__ __nv_bfloat16 g_KVlo[(size_t)BH*Dd*Dd];            // 0.5 MB

// ---------------- helpers ----------------
__device__ __forceinline__ uint32_t s2u(const void* p) {
    uint32_t a;
    asm("{ .reg .u64 t; cvta.to.shared.u64 t, %1; cvt.u32.u64 %0, t; }" : "=r"(a) : "l"(p));
    return a;
}
__device__ __forceinline__ void ldsm4t(uint32_t addr, uint32_t* r) {
    asm volatile("ldmatrix.sync.aligned.m8n8.x4.trans.shared.b16 {%0,%1,%2,%3}, [%4];"
                 : "=r"(r[0]), "=r"(r[1]), "=r"(r[2]), "=r"(r[3]) : "r"(addr));
}
__device__ __forceinline__ void ldsm4(uint32_t addr, uint32_t* r) {
    asm volatile("ldmatrix.sync.aligned.m8n8.x4.shared.b16 {%0,%1,%2,%3}, [%4];"
                 : "=r"(r[0]), "=r"(r[1]), "=r"(r[2]), "=r"(r[3]) : "r"(addr));
}
__device__ __forceinline__ void mma16816(float* c, const uint32_t* a, uint32_t b0, uint32_t b1) {
    asm volatile("mma.sync.aligned.m16n8k16.row.col.f32.bf16.bf16.f32 "
                 "{%0,%1,%2,%3},{%4,%5,%6,%7},{%8,%9},{%0,%1,%2,%3};"
                 : "+f"(c[0]), "+f"(c[1]), "+f"(c[2]), "+f"(c[3])
                 : "r"(a[0]), "r"(a[1]), "r"(a[2]), "r"(a[3]), "r"(b0), "r"(b1));
}
__device__ __forceinline__ float elu_p1(float x) { float e = __expf(x); return x > 0.0f ? x + 1.0f : e; }
__device__ __forceinline__ float rbf(float x) { return __bfloat162float(__float2bfloat16_rn(x)); }
__device__ __forceinline__ uint32_t pk(float a, float b) {
    return ((uint32_t)__bfloat16_as_ushort(__float2bfloat16_rn(b)) << 16) |
            (uint32_t)__bfloat16_as_ushort(__float2bfloat16_rn(a));
}

// ============================================================
// Phase 1: partial KV[d][e] = sum_l Kf[l][d]*Vm[l][e]  (Kf^T @ Vm)
// grid (NCHUNK, BH), 256 thr / 8 warps. Warp w: d-strip (w&3)*16, e-strip (w>>2)*32.
// ============================================================
__global__ void __launch_bounds__(256, 3)
phase1_kernel(const float* __restrict__ Kp, const float* __restrict__ Vp,
              const float* __restrict__ maskp, const float* __restrict__ pip,
              const float* __restrict__ mup) {
    __shared__ __nv_bfloat16 khi[64*PAD], klo[64*PAD], vhi[64*PAD], vlo[64*PAD];
    __shared__ float mus[64];
    const int t = threadIdx.x, lane = t & 31, w = t >> 5;
    const int chunk = blockIdx.x, bhidx = blockIdx.y, b = bhidx / Hh, h = bhidx % Hh;

    const float p0 = fminf(fmaxf(pip[0], 0.f), 1.f);
    const float p1 = fminf(fmaxf(pip[1], 0.f), 1.f);
    const float ps = p0 + p1;
    if (t < 64) mus[t] = p0 * mup[h*64 + t] + p1 * mup[(Hh + h)*64 + t];
    __syncthreads();

    const size_t base = ((size_t)bhidx*Ll + (size_t)chunk*RPC) * 64;
    const float* __restrict__ Kb = Kp + base;
    const float* __restrict__ Vb = Vp + base;
    const float* __restrict__ mb = maskp + (size_t)b*Ll + (size_t)chunk*RPC;

    const int md = (w & 3) * 16, ne = (w >> 2) * 32;
    const int gr = lane >> 3, r8 = lane & 7;
    // a-frag (trans ldmatrix of K stored [l][d]): mats (m0k0),(m8k0),(m0k8),(m8k8)
    const uint32_t aoff = ((uint32_t)((((gr & 2) ? 8 : 0) + r8) * PAD + md + ((gr & 1) ? 8 : 0))) * 2;
    // b-frag (trans ldmatrix of V stored [l][e]): mats (k0n0),(k8n0),(k0n8),(k8n8)
    const uint32_t boff = ((uint32_t)((((gr & 1) ? 8 : 0) + r8) * PAD + ne + ((gr & 2) ? 8 : 0))) * 2;
    const uint32_t skh = s2u(khi), skl = s2u(klo), svh = s2u(vhi), svl = s2u(vlo);

    float acc[4][4];
#pragma unroll
    for (int i = 0; i < 4; i++)
#pragma unroll
        for (int j = 0; j < 4; j++) acc[i][j] = 0.f;

    for (int tile = 0; tile < NTILE; tile++) {
        __syncthreads();   // previous tile's MMAs done before smem overwrite
        const int l0 = tile * 64;
#pragma unroll
        for (int j = 0; j < 4; j++) {     // 1024 float4 per tensor, 256 threads
            const int idx = t + 256*j;
            const int row = idx >> 4, dq = (idx & 15) * 4;
            const size_t off = (size_t)(l0 + row)*64 + dq;
            float4 kq = *(const float4*)(Kb + off);
            float4 vq = *(const float4*)(Vb + off);
            const float m = mb[l0 + row], msc = m * SCALE;
            float f0 = elu_p1(kq.x*ps - mus[dq+0]) * msc;
            float f1 = elu_p1(kq.y*ps - mus[dq+1]) * msc;
            float f2 = elu_p1(kq.z*ps - mus[dq+2]) * msc;
            float f3 = elu_p1(kq.w*ps - mus[dq+3]) * msc;
            uint2 kh = { pk(f0, f1), pk(f2, f3) };
            uint2 kl2 = { pk(f0 - rbf(f0), f1 - rbf(f1)), pk(f2 - rbf(f2), f3 - rbf(f3)) };
            *(uint2*)&khi[row*PAD + dq] = kh;
            *(uint2*)&klo[row*PAD + dq] = kl2;
            float g0 = vq.x * m, g1 = vq.y * m, g2 = vq.z * m, g3 = vq.w * m;
            uint2 vh2 = { pk(g0, g1), pk(g2, g3) };
            uint2 vl2 = { pk(g0 - rbf(g0), g1 - rbf(g1)), pk(g2 - rbf(g2), g3 - rbf(g3)) };
            *(uint2*)&vhi[row*PAD + dq] = vh2;
            *(uint2*)&vlo[row*PAD + dq] = vl2;
        }
        __syncthreads();

#pragma unroll
        for (int kl = 0; kl < 64; kl += 16) {
            const uint32_t kadd = (uint32_t)(kl * PAD * 2);
            uint32_t ah[4], al[4];
            ldsm4t(skh + kadd + aoff, ah);
            ldsm4t(skl + kadd + aoff, al);
            uint32_t bh0[4], bl0[4], bh1[4], bl1[4];
            ldsm4t(svh + kadd + boff,      bh0);
            ldsm4t(svl + kadd + boff,      bl0);
            ldsm4t(svh + kadd + boff + 32, bh1);   // +16 cols * 2B
            ldsm4t(svl + kadd + boff + 32, bl1);
            mma16816(acc[0], ah, bh0[0], bh0[1]);
            mma16816(acc[0], ah, bl0[0], bl0[1]);
            mma16816(acc[0], al, bh0[0], bh0[1]);
            mma16816(acc[1], ah, bh0[2], bh0[3]);
            mma16816(acc[1], ah, bl0[2], bl0[3]);
            mma16816(acc[1], al, bh0[2], bh0[3]);
            mma16816(acc[2], ah, bh1[0], bh1[1]);
            mma16816(acc[2], ah, bl1[0], bl1[1]);
            mma16816(acc[2], al, bh1[0], bh1[1]);
            mma16816(acc[3], ah, bh1[2], bh1[3]);
            mma16816(acc[3], ah, bl1[2], bl1[3]);
            mma16816(acc[3], al, bh1[2], bh1[3]);
        }
    }

    // epilogue: c-frag layout (row = lane/4 (+8), col = 2*(lane%4) (+1))
    float* outp = g_scratch + ((size_t)chunk*BH + bhidx) * 4096;
    const int rw = lane >> 2, cq = (lane & 3) * 2;
#pragma unroll
    for (int j = 0; j < 4; j++) {
        float2 lo = { acc[j][0], acc[j][1] };
        float2 hi = { acc[j][2], acc[j][3] };
        *(float2*)&outp[(md + rw) * 64 + ne + 8*j + cq]     = lo;
        *(float2*)&outp[(md + 8 + rw) * 64 + ne + 8*j + cq] = hi;
    }
}

// ============================================================
// Reduce: KV = sum over chunks; emit bf16 hi/lo
// ============================================================
__global__ void __launch_bounds__(256)
reduce_kernel() {
    const int bhidx = blockIdx.x, t = threadIdx.x;
#pragma unroll
    for (int i = 0; i < 4; i++) {
        const int pos = t*4 + i*1024;
        float4 s = make_float4(0.f, 0.f, 0.f, 0.f);
#pragma unroll
        for (int c = 0; c < NCHUNK; c++) {
            const float4 v = *(const float4*)(g_scratch + ((size_t)c*BH + bhidx)*4096 + pos);
            s.x += v.x; s.y += v.y; s.z += v.z; s.w += v.w;
        }
        uint2 hi = { pk(s.x, s.y), pk(s.z, s.w) };
        uint2 lo = { pk(s.x - rbf(s.x), s.y - rbf(s.y)), pk(s.z - rbf(s.z), s.w - rbf(s.w)) };
        *(uint2*)(g_KVhi + (size_t)bhidx*4096 + pos) = hi;
        *(uint2*)(g_KVlo + (size_t)bhidx*4096 + pos) = lo;
    }
}

// ============================================================
// Phase 2: out[l][e] = sum_d Qf[l][d]*KV[d][e]
// grid (L/128, BH), 256 thr / 8 warps. Warp w: l-strip w*16, all 64 e.
// ============================================================
__global__ void __launch_bounds__(256, 2)
phase2_kernel(const float* __restrict__ Qp, float* __restrict__ outp) {
    extern __shared__ __nv_bfloat16 sm2[];
    __nv_bfloat16* qhi = sm2;                          // 128*PAD
    __nv_bfloat16* qlo = sm2 + 128*PAD;
    __nv_bfloat16* kvh = sm2 + 2*128*PAD;              // 64*PAD
    __nv_bfloat16* kvl = sm2 + 2*128*PAD + 64*PAD;
    const int t = threadIdx.x, lane = t & 31, w = t >> 5;
    const int rb = blockIdx.x, bhidx = blockIdx.y;

    // KV tiles (8 KB each) — 16B chunks, padded rows
#pragma unroll
    for (int i = 0; i < 2; i++) {
        const int idx8 = t + 256*i;                    // 512 groups of 8 bf16
        const int row = idx8 >> 3, cg = (idx8 & 7) * 8;
        *(uint4*)&kvh[row*PAD + cg] = *(const uint4*)(g_KVhi + (size_t)bhidx*4096 + row*64 + cg);
        *(uint4*)&kvl[row*PAD + cg] = *(const uint4*)(g_KVlo + (size_t)bhidx*4096 + row*64 + cg);
    }
    // Q: 128 rows, transform + split
    const float* __restrict__ Qb = Qp + ((size_t)bhidx*Ll + (size_t)rb*128) * 64;
#pragma unroll
    for (int j = 0; j < 8; j++) {
        const int idx = t + 256*j;                     // 2048 float4
        const int row = idx >> 4, dq = (idx & 15) * 4;
        float4 q = *(const float4*)(Qb + (size_t)row*64 + dq);
        float f0 = elu_p1(q.x) * SCALE, f1 = elu_p1(q.y) * SCALE;
        float f2 = elu_p1(q.z) * SCALE, f3 = elu_p1(q.w) * SCALE;
        uint2 qh = { pk(f0, f1), pk(f2, f3) };
        uint2 ql = { pk(f0 - rbf(f0), f1 - rbf(f1)), pk(f2 - rbf(f2), f3 - rbf(f3)) };
        *(uint2*)&qhi[row*PAD + dq] = qh;
        *(uint2*)&qlo[row*PAD + dq] = ql;
    }
    __syncthreads();

    const int l0 = w * 16;
    const int gr = lane >> 3, r8 = lane & 7;
    // a-frag (normal ldmatrix of Q [l][d]): mats (m0k0),(m8k0),(m0k8),(m8k8)
    const uint32_t aoff = ((uint32_t)((l0 + ((gr & 1) ? 8 : 0) + r8) * PAD + ((gr & 2) ? 8 : 0))) * 2;
    // b-frag (trans ldmatrix of KV [d][e])
    const uint32_t boff = ((uint32_t)((((gr & 1) ? 8 : 0) + r8) * PAD + ((gr & 2) ? 8 : 0))) * 2;
    const uint32_t sqh = s2u(qhi), sql = s2u(qlo), svh = s2u(kvh), svl = s2u(kvl);

    float acc[8][4];
#pragma unroll
    for (int i = 0; i < 8; i++)
#pragma unroll
        for (int j = 0; j < 4; j++) acc[i][j] = 0.f;

#pragma unroll
    for (int kd = 0; kd < 64; kd += 16) {
        uint32_t ah[4], al[4];
        ldsm4(sqh + aoff + (uint32_t)(kd*2), ah);
        ldsm4(sql + aoff + (uint32_t)(kd*2), al);
#pragma unroll
        for (int p = 0; p < 4; p++) {                  // n-pair p: tiles 2p, 2p+1
            const uint32_t badd = (uint32_t)(kd * PAD * 2 + p * 32);
            uint32_t vh[4], vl[4];
            ldsm4t(svh + badd + boff, vh);
            ldsm4t(svl + badd + boff, vl);
            mma16816(acc[2*p], ah, vh[0], vh[1]);
            mma16816(acc[2*p], ah, vl[0], vl[1]);
            mma16816(acc[2*p], al, vh[0], vh[1]);
            mma16816(acc[2*p+1], ah, vh[2], vh[3]);
            mma16816(acc[2*p+1], ah, vl[2], vl[3]);
            mma16816(acc[2*p+1], al, vh[2], vh[3]);
        }
    }

    float* __restrict__ ob = outp + ((size_t)bhidx*Ll + (size_t)rb*128) * 64;
    const int rw = lane >> 2, cq = (lane & 3) * 2;
#pragma unroll
    for (int j = 0; j < 8; j++) {
        float2 lo = { acc[j][0], acc[j][1] };
        float2 hi = { acc[j][2], acc[j][3] };
        *(float2*)&ob[(l0 + rw) * 64 + 8*j + cq]     = lo;
        *(float2*)&ob[(l0 + 8 + rw) * 64 + 8*j + cq] = hi;
    }
}

// ============================================================
// Launch
// ============================================================
extern "C" void kernel_launch(void* const* d_in, const int* in_sizes, int n_in,
                              void* d_out, int out_size) {
    const float* Q    = (const float*)d_in[0];
    const float* K    = (const float*)d_in[1];
    const float* V    = (const float*)d_in[2];
    const float* mask = (const float*)d_in[3];
    const float* pi   = (const float*)d_in[4];
    const float* mu   = (const float*)d_in[5];
    float* out = (float*)d_out;

    static int smem_set = 0;
    const int p2_smem = (2*128 + 2*64) * PAD * 2;   // 55296 B
    if (!smem_set) {
        cudaFuncSetAttribute(phase2_kernel, cudaFuncAttributeMaxDynamicSharedMemorySize, p2_smem);
        smem_set = 1;
    }

    dim3 g1(NCHUNK, BH);
    phase1_kernel<<<g1, 256>>>(K, V, mask, pi, mu);
    reduce_kernel<<<BH, 256>>>();
    dim3 g3(Ll / 128, BH);
    phase2_kernel<<<g3, 256, p2_smem>>>(Q, out);
}

// round 5
// speedup vs baseline: 1.5288x; 1.1195x over previous
#include <cuda_runtime.h>
#include <cuda_bf16.h>
#include <cstdint>

#define Bb 4
#define Hh 16
#define Ll 8192
#define Dd 64
#define BH (Bb*Hh)
#define SCALE 0.10511205190671431f   // 8192^(-1/4)
#define NCHUNK 16
#define RPC (Ll/NCHUNK)              // 512 rows per chunk
#define NTILE (RPC/64)               // 8 tiles of 64 rows
#define PAD 72                       // bf16 row stride (144B, 16B-multiple, conflict-free)

// __device__ scratch (allocation-free rule)
__device__ float g_scratch[(size_t)NCHUNK*BH*Dd*Dd];          // 16.7 MB fp32 partial KV
__device__ __nv_bfloat16 g_KVhi[(size_t)BH*Dd*Dd];            // 0.5 MB
__device__ __nv_bfloat16 g_KVlo[(size_t)BH*Dd*Dd];            // 0.5 MB

// ---------------- helpers ----------------
__device__ __forceinline__ uint32_t s2u(const void* p) {
    uint32_t a;
    asm("{ .reg .u64 t; cvta.to.shared.u64 t, %1; cvt.u32.u64 %0, t; }" : "=r"(a) : "l"(p));
    return a;
}
__device__ __forceinline__ void ldsm4t(uint32_t addr, uint32_t* r) {
    asm volatile("ldmatrix.sync.aligned.m8n8.x4.trans.shared.b16 {%0,%1,%2,%3}, [%4];"
                 : "=r"(r[0]), "=r"(r[1]), "=r"(r[2]), "=r"(r[3]) : "r"(addr));
}
__device__ __forceinline__ void ldsm4(uint32_t addr, uint32_t* r) {
    asm volatile("ldmatrix.sync.aligned.m8n8.x4.shared.b16 {%0,%1,%2,%3}, [%4];"
                 : "=r"(r[0]), "=r"(r[1]), "=r"(r[2]), "=r"(r[3]) : "r"(addr));
}
__device__ __forceinline__ void mma16816(float* c, const uint32_t* a, uint32_t b0, uint32_t b1) {
    asm volatile("mma.sync.aligned.m16n8k16.row.col.f32.bf16.bf16.f32 "
                 "{%0,%1,%2,%3},{%4,%5,%6,%7},{%8,%9},{%0,%1,%2,%3};"
                 : "+f"(c[0]), "+f"(c[1]), "+f"(c[2]), "+f"(c[3])
                 : "r"(a[0]), "r"(a[1]), "r"(a[2]), "r"(a[3]), "r"(b0), "r"(b1));
}
__device__ __forceinline__ float elu_p1(float x) { float e = __expf(x); return x > 0.0f ? x + 1.0f : e; }
__device__ __forceinline__ float rbf(float x) { return __bfloat162float(__float2bfloat16_rn(x)); }
__device__ __forceinline__ uint32_t pk(float a, float b) {
    return ((uint32_t)__bfloat16_as_ushort(__float2bfloat16_rn(b)) << 16) |
            (uint32_t)__bfloat16_as_ushort(__float2bfloat16_rn(a));
}

// ============================================================
// Phase 1: partial KV[d][e] = sum_l Kf[l][d]*Vm[l][e]  (Kf^T @ Vm)
// grid (NCHUNK, BH), 256 thr / 8 warps, software-pipelined global loads.
// ============================================================
__global__ void __launch_bounds__(256)
phase1_kernel(const float* __restrict__ Kp, const float* __restrict__ Vp,
              const float* __restrict__ maskp, const float* __restrict__ pip,
              const float* __restrict__ mup) {
    __shared__ __nv_bfloat16 khi[64*PAD], klo[64*PAD], vhi[64*PAD], vlo[64*PAD];
    __shared__ float mus[64];
    const int t = threadIdx.x, lane = t & 31, w = t >> 5;
    const int chunk = blockIdx.x, bhidx = blockIdx.y, b = bhidx / Hh, h = bhidx % Hh;

    const float p0 = fminf(fmaxf(pip[0], 0.f), 1.f);
    const float p1 = fminf(fmaxf(pip[1], 0.f), 1.f);
    const float ps = p0 + p1;
    if (t < 64) mus[t] = p0 * mup[h*64 + t] + p1 * mup[(Hh + h)*64 + t];

    const size_t base = ((size_t)bhidx*Ll + (size_t)chunk*RPC) * 64;
    const float* __restrict__ Kb = Kp + base;
    const float* __restrict__ Vb = Vp + base;
    const float* __restrict__ mb = maskp + (size_t)b*Ll + (size_t)chunk*RPC;

    const int md = (w & 3) * 16, ne = (w >> 2) * 32;
    const int gr = lane >> 3, r8 = lane & 7;
    const uint32_t aoff = ((uint32_t)((((gr & 2) ? 8 : 0) + r8) * PAD + md + ((gr & 1) ? 8 : 0))) * 2;
    const uint32_t boff = ((uint32_t)((((gr & 1) ? 8 : 0) + r8) * PAD + ne + ((gr & 2) ? 8 : 0))) * 2;
    const uint32_t skh = s2u(khi), skl = s2u(klo), svh = s2u(vhi), svl = s2u(vlo);

    float acc[4][4];
#pragma unroll
    for (int i = 0; i < 4; i++)
#pragma unroll
        for (int j = 0; j < 4; j++) acc[i][j] = 0.f;

    float4 kreg[4], vreg[4];
    float  mreg[4];

#define LOAD_TILE(tl) do { const int _l0 = (tl) * 64; \
    _Pragma("unroll") \
    for (int j = 0; j < 4; j++) { \
        const int idx = t + 256*j, row = idx >> 4, dq = (idx & 15) * 4; \
        const size_t off = (size_t)(_l0 + row)*64 + dq; \
        kreg[j] = *(const float4*)(Kb + off); \
        vreg[j] = *(const float4*)(Vb + off); \
        mreg[j] = mb[_l0 + row]; \
    } } while (0)

    LOAD_TILE(0);

    for (int tile = 0; tile < NTILE; tile++) {
        __syncthreads();   // previous tile's MMAs done reading smem
        // transform current registers -> smem tiles
#pragma unroll
        for (int j = 0; j < 4; j++) {
            const int idx = t + 256*j, row = idx >> 4, dq = (idx & 15) * 4;
            const float m = mreg[j], msc = m * SCALE;
            float f0 = elu_p1(kreg[j].x*ps - mus[dq+0]) * msc;
            float f1 = elu_p1(kreg[j].y*ps - mus[dq+1]) * msc;
            float f2 = elu_p1(kreg[j].z*ps - mus[dq+2]) * msc;
            float f3 = elu_p1(kreg[j].w*ps - mus[dq+3]) * msc;
            uint2 kh = { pk(f0, f1), pk(f2, f3) };
            uint2 kl2 = { pk(f0 - rbf(f0), f1 - rbf(f1)), pk(f2 - rbf(f2), f3 - rbf(f3)) };
            *(uint2*)&khi[row*PAD + dq] = kh;
            *(uint2*)&klo[row*PAD + dq] = kl2;
            float g0 = vreg[j].x * m, g1 = vreg[j].y * m;
            float g2 = vreg[j].z * m, g3 = vreg[j].w * m;
            uint2 vh2 = { pk(g0, g1), pk(g2, g3) };
            uint2 vl2 = { pk(g0 - rbf(g0), g1 - rbf(g1)), pk(g2 - rbf(g2), g3 - rbf(g3)) };
            *(uint2*)&vhi[row*PAD + dq] = vh2;
            *(uint2*)&vlo[row*PAD + dq] = vl2;
        }
        // issue next tile's global loads; latency hides under this tile's MMAs
        if (tile + 1 < NTILE) LOAD_TILE(tile + 1);
        __syncthreads();

#pragma unroll
        for (int kl = 0; kl < 64; kl += 16) {
            const uint32_t kadd = (uint32_t)(kl * PAD * 2);
            uint32_t ah[4], al[4];
            ldsm4t(skh + kadd + aoff, ah);
            ldsm4t(skl + kadd + aoff, al);
            uint32_t bh0[4], bl0[4], bh1[4], bl1[4];
            ldsm4t(svh + kadd + boff,      bh0);
            ldsm4t(svl + kadd + boff,      bl0);
            ldsm4t(svh + kadd + boff + 32, bh1);
            ldsm4t(svl + kadd + boff + 32, bl1);
            mma16816(acc[0], ah, bh0[0], bh0[1]);
            mma16816(acc[0], ah, bl0[0], bl0[1]);
            mma16816(acc[0], al, bh0[0], bh0[1]);
            mma16816(acc[1], ah, bh0[2], bh0[3]);
            mma16816(acc[1], ah, bl0[2], bl0[3]);
            mma16816(acc[1], al, bh0[2], bh0[3]);
            mma16816(acc[2], ah, bh1[0], bh1[1]);
            mma16816(acc[2], ah, bl1[0], bl1[1]);
            mma16816(acc[2], al, bh1[0], bh1[1]);
            mma16816(acc[3], ah, bh1[2], bh1[3]);
            mma16816(acc[3], ah, bl1[2], bl1[3]);
            mma16816(acc[3], al, bh1[2], bh1[3]);
        }
    }
#undef LOAD_TILE

    float* outp = g_scratch + ((size_t)chunk*BH + bhidx) * 4096;
    const int rw = lane >> 2, cq = (lane & 3) * 2;
#pragma unroll
    for (int j = 0; j < 4; j++) {
        float2 lo = { acc[j][0], acc[j][1] };
        float2 hi = { acc[j][2], acc[j][3] };
        *(float2*)&outp[(md + rw) * 64 + ne + 8*j + cq]     = lo;
        *(float2*)&outp[(md + 8 + rw) * 64 + ne + 8*j + cq] = hi;
    }
}

// ============================================================
// Reduce: KV = sum over chunks; emit bf16 hi/lo
// ============================================================
__global__ void __launch_bounds__(256)
reduce_kernel() {
    const int bhidx = blockIdx.x, t = threadIdx.x;
#pragma unroll
    for (int i = 0; i < 4; i++) {
        const int pos = t*4 + i*1024;
        float4 s = make_float4(0.f, 0.f, 0.f, 0.f);
#pragma unroll
        for (int c = 0; c < NCHUNK; c++) {
            const float4 v = *(const float4*)(g_scratch + ((size_t)c*BH + bhidx)*4096 + pos);
            s.x += v.x; s.y += v.y; s.z += v.z; s.w += v.w;
        }
        uint2 hi = { pk(s.x, s.y), pk(s.z, s.w) };
        uint2 lo = { pk(s.x - rbf(s.x), s.y - rbf(s.y)), pk(s.z - rbf(s.z), s.w - rbf(s.w)) };
        *(uint2*)(g_KVhi + (size_t)bhidx*4096 + pos) = hi;
        *(uint2*)(g_KVlo + (size_t)bhidx*4096 + pos) = lo;
    }
}

// ============================================================
// Phase 2: out[l][e] = sum_d Qf[l][d]*KV[d][e]
// grid (L/64, BH), 128 thr / 4 warps, 64 Q rows per CTA (static 36KB smem,
// ~5 CTAs/SM for latency hiding). Warp w: l-strip w*16, all 64 e.
// ============================================================
__global__ void __launch_bounds__(128)
phase2_kernel(const float* __restrict__ Qp, float* __restrict__ outp) {
    __shared__ __nv_bfloat16 qhi[64*PAD], qlo[64*PAD], kvh[64*PAD], kvl[64*PAD];
    const int t = threadIdx.x, lane = t & 31, w = t >> 5;
    const int rb = blockIdx.x, bhidx = blockIdx.y;

    // Q rows: issue global loads first (latency overlaps KV copy below)
    const float* __restrict__ Qb = Qp + ((size_t)bhidx*Ll + (size_t)rb*64) * 64;
    float4 qreg[8];
#pragma unroll
    for (int j = 0; j < 8; j++) {
        const int idx = t + 128*j, row = idx >> 4, dq = (idx & 15) * 4;
        qreg[j] = *(const float4*)(Qb + (size_t)row*64 + dq);
    }
    // KV tiles (8 KB each hi/lo)
#pragma unroll
    for (int i = 0; i < 4; i++) {
        const int idx8 = t + 128*i;                    // 512 groups of 8 bf16
        const int row = idx8 >> 3, cg = (idx8 & 7) * 8;
        *(uint4*)&kvh[row*PAD + cg] = *(const uint4*)(g_KVhi + (size_t)bhidx*4096 + row*64 + cg);
        *(uint4*)&kvl[row*PAD + cg] = *(const uint4*)(g_KVlo + (size_t)bhidx*4096 + row*64 + cg);
    }
    // transform Q -> smem hi/lo
#pragma unroll
    for (int j = 0; j < 8; j++) {
        const int idx = t + 128*j, row = idx >> 4, dq = (idx & 15) * 4;
        float f0 = elu_p1(qreg[j].x) * SCALE, f1 = elu_p1(qreg[j].y) * SCALE;
        float f2 = elu_p1(qreg[j].z) * SCALE, f3 = elu_p1(qreg[j].w) * SCALE;
        uint2 qh = { pk(f0, f1), pk(f2, f3) };
        uint2 ql = { pk(f0 - rbf(f0), f1 - rbf(f1)), pk(f2 - rbf(f2), f3 - rbf(f3)) };
        *(uint2*)&qhi[row*PAD + dq] = qh;
        *(uint2*)&qlo[row*PAD + dq] = ql;
    }
    __syncthreads();

    const int l0 = w * 16;
    const int gr = lane >> 3, r8 = lane & 7;
    const uint32_t aoff = ((uint32_t)((l0 + ((gr & 1) ? 8 : 0) + r8) * PAD + ((gr & 2) ? 8 : 0))) * 2;
    const uint32_t boff = ((uint32_t)((((gr & 1) ? 8 : 0) + r8) * PAD + ((gr & 2) ? 8 : 0))) * 2;
    const uint32_t sqh = s2u(qhi), sql = s2u(qlo), svh = s2u(kvh), svl = s2u(kvl);

    float acc[8][4];
#pragma unroll
    for (int i = 0; i < 8; i++)
#pragma unroll
        for (int j = 0; j < 4; j++) acc[i][j] = 0.f;

#pragma unroll
    for (int kd = 0; kd < 64; kd += 16) {
        uint32_t ah[4], al[4];
        ldsm4(sqh + aoff + (uint32_t)(kd*2), ah);
        ldsm4(sql + aoff + (uint32_t)(kd*2), al);
#pragma unroll
        for (int p = 0; p < 4; p++) {
            const uint32_t badd = (uint32_t)(kd * PAD * 2 + p * 32);
            uint32_t vh[4], vl[4];
            ldsm4t(svh + badd + boff, vh);
            ldsm4t(svl + badd + boff, vl);
            mma16816(acc[2*p], ah, vh[0], vh[1]);
            mma16816(acc[2*p], ah, vl[0], vl[1]);
            mma16816(acc[2*p], al, vh[0], vh[1]);
            mma16816(acc[2*p+1], ah, vh[2], vh[3]);
            mma16816(acc[2*p+1], ah, vl[2], vl[3]);
            mma16816(acc[2*p+1], al, vh[2], vh[3]);
        }
    }

    float* __restrict__ ob = outp + ((size_t)bhidx*Ll + (size_t)rb*64) * 64;
    const int rw = lane >> 2, cq = (lane & 3) * 2;
#pragma unroll
    for (int j = 0; j < 8; j++) {
        float2 lo = { acc[j][0], acc[j][1] };
        float2 hi = { acc[j][2], acc[j][3] };
        *(float2*)&ob[(l0 + rw) * 64 + 8*j + cq]     = lo;
        *(float2*)&ob[(l0 + 8 + rw) * 64 + 8*j + cq] = hi;
    }
}

// ============================================================
// Launch
// ============================================================
extern "C" void kernel_launch(void* const* d_in, const int* in_sizes, int n_in,
                              void* d_out, int out_size) {
    const float* Q    = (const float*)d_in[0];
    const float* K    = (const float*)d_in[1];
    const float* V    = (const float*)d_in[2];
    const float* mask = (const float*)d_in[3];
    const float* pi   = (const float*)d_in[4];
    const float* mu   = (const float*)d_in[5];
    float* out = (float*)d_out;

    dim3 g1(NCHUNK, BH);
    phase1_kernel<<<g1, 256>>>(K, V, mask, pi, mu);
    reduce_kernel<<<BH, 256>>>();
    dim3 g3(Ll / 64, BH);
    phase2_kernel<<<g3, 128>>>(Q, out);
}

// round 6
// speedup vs baseline: 1.5370x; 1.0053x over previous
#include <cuda_runtime.h>
#include <cuda_bf16.h>
#include <cstdint>

#define Bb 4
#define Hh 16
#define Ll 8192
#define Dd 64
#define BH (Bb*Hh)
#define SCALE 0.10511205190671431f   // 8192^(-1/4)
#define NCHUNK 16
#define RPC (Ll/NCHUNK)              // 512 rows per chunk
#define NTILE (RPC/64)               // 8 tiles of 64 rows
#define PAD 72                       // bf16 row stride (144B, conflict-free)

// __device__ scratch (allocation-free rule)
__device__ float g_scratch[(size_t)NCHUNK*BH*Dd*Dd];          // 16.7 MB fp32 partial KV
__device__ __nv_bfloat16 g_KVhi[(size_t)BH*Dd*Dd];            // 0.5 MB
__device__ __nv_bfloat16 g_KVlo[(size_t)BH*Dd*Dd];            // 0.5 MB

// ---------------- helpers ----------------
__device__ __forceinline__ uint32_t s2u(const void* p) {
    uint32_t a;
    asm("{ .reg .u64 t; cvta.to.shared.u64 t, %1; cvt.u32.u64 %0, t; }" : "=r"(a) : "l"(p));
    return a;
}
__device__ __forceinline__ void cp16(uint32_t dst, const void* src) {
    asm volatile("cp.async.cg.shared.global [%0], [%1], 16;" :: "r"(dst), "l"(src) : "memory");
}
#define CPCOMMIT() asm volatile("cp.async.commit_group;" ::: "memory")
#define CPWAIT(n)  asm volatile("cp.async.wait_group %0;" :: "n"(n) : "memory")
__device__ __forceinline__ void ldsm4t(uint32_t addr, uint32_t* r) {
    asm volatile("ldmatrix.sync.aligned.m8n8.x4.trans.shared.b16 {%0,%1,%2,%3}, [%4];"
                 : "=r"(r[0]), "=r"(r[1]), "=r"(r[2]), "=r"(r[3]) : "r"(addr));
}
__device__ __forceinline__ void ldsm4(uint32_t addr, uint32_t* r) {
    asm volatile("ldmatrix.sync.aligned.m8n8.x4.shared.b16 {%0,%1,%2,%3}, [%4];"
                 : "=r"(r[0]), "=r"(r[1]), "=r"(r[2]), "=r"(r[3]) : "r"(addr));
}
__device__ __forceinline__ void mma16816(float* c, const uint32_t* a, uint32_t b0, uint32_t b1) {
    asm volatile("mma.sync.aligned.m16n8k16.row.col.f32.bf16.bf16.f32 "
                 "{%0,%1,%2,%3},{%4,%5,%6,%7},{%8,%9},{%0,%1,%2,%3};"
                 : "+f"(c[0]), "+f"(c[1]), "+f"(c[2]), "+f"(c[3])
                 : "r"(a[0]), "r"(a[1]), "r"(a[2]), "r"(a[3]), "r"(b0), "r"(b1));
}
__device__ __forceinline__ float elu_p1(float x) { float e = __expf(x); return x > 0.0f ? x + 1.0f : e; }
__device__ __forceinline__ float rbf(float x) { return __bfloat162float(__float2bfloat16_rn(x)); }
__device__ __forceinline__ uint32_t pk(float a, float b) {
    return ((uint32_t)__bfloat16_as_ushort(__float2bfloat16_rn(b)) << 16) |
            (uint32_t)__bfloat16_as_ushort(__float2bfloat16_rn(a));
}

// phase1 dynamic smem layout (bytes)
#define P1_STK 0            // 2 x 16384 fp32 staging K
#define P1_STV 32768        // 2 x 16384 fp32 staging V
#define P1_KHI 65536
#define P1_KLO 74752
#define P1_VHI 83968
#define P1_VLO 93184
#define P1_MSK 102400       // 512 fp32
#define P1_MUS 104448       // 64 fp32
#define P1_SZ  104704
// phase2 dynamic smem layout
#define P2_STQ 0            // 2 x 16384 fp32 staging Q
#define P2_QHI 32768
#define P2_QLO 41984
#define P2_KVH 51200
#define P2_KVL 60416
#define P2_SZ  69632

// ============================================================
// Phase 1: partial KV[d][e] = sum_l Kf[l][d]*Vm[l][e]
// grid (NCHUNK, BH), 256 thr / 8 warps, cp.async double-buffered staging.
// ============================================================
__global__ void __launch_bounds__(256, 2)
phase1_kernel(const float* __restrict__ Kp, const float* __restrict__ Vp,
              const float* __restrict__ maskp, const float* __restrict__ pip,
              const float* __restrict__ mup) {
    extern __shared__ char smem[];
    const uint32_t sb = s2u(smem);
    float* msk = (float*)(smem + P1_MSK);
    float* mus = (float*)(smem + P1_MUS);
    const int t = threadIdx.x, lane = t & 31, w = t >> 5;
    const int chunk = blockIdx.x, bhidx = blockIdx.y, b = bhidx / Hh, h = bhidx % Hh;

    const float p0 = fminf(fmaxf(pip[0], 0.f), 1.f);
    const float p1 = fminf(fmaxf(pip[1], 0.f), 1.f);
    const float ps = p0 + p1;
    if (t < 64) mus[t] = p0 * mup[h*64 + t] + p1 * mup[(Hh + h)*64 + t];

    const size_t base = ((size_t)bhidx*Ll + (size_t)chunk*RPC) * 64;
    const float* __restrict__ Kb = Kp + base;
    const float* __restrict__ Vb = Vp + base;
    const float* __restrict__ mb = maskp + (size_t)b*Ll + (size_t)chunk*RPC;
    msk[t] = mb[t]; msk[t + 256] = mb[t + 256];

    // issue staging for tiles 0 and 1
#pragma unroll
    for (int st = 0; st < 2; st++) {
        const float* ks = Kb + st*4096;
        const float* vs = Vb + st*4096;
        const uint32_t kd = sb + P1_STK + st*16384, vd = sb + P1_STV + st*16384;
#pragma unroll
        for (int j = 0; j < 4; j++) {
            const int u = t + 256*j;
            cp16(kd + u*16, ks + u*4);
            cp16(vd + u*16, vs + u*4);
        }
        CPCOMMIT();
    }

    const int md = (w & 3) * 16, ne = (w >> 2) * 32;
    const int gr = lane >> 3, r8 = lane & 7;
    const uint32_t aoff = ((uint32_t)((((gr & 2) ? 8 : 0) + r8) * PAD + md + ((gr & 1) ? 8 : 0))) * 2;
    const uint32_t boff = ((uint32_t)((((gr & 1) ? 8 : 0) + r8) * PAD + ne + ((gr & 2) ? 8 : 0))) * 2;
    const uint32_t skh = sb + P1_KHI, skl = sb + P1_KLO, svh = sb + P1_VHI, svl = sb + P1_VLO;
    __nv_bfloat16* khi = (__nv_bfloat16*)(smem + P1_KHI);
    __nv_bfloat16* klo = (__nv_bfloat16*)(smem + P1_KLO);
    __nv_bfloat16* vhi = (__nv_bfloat16*)(smem + P1_VHI);
    __nv_bfloat16* vlo = (__nv_bfloat16*)(smem + P1_VLO);

    float acc[4][4];
#pragma unroll
    for (int i = 0; i < 4; i++)
#pragma unroll
        for (int j = 0; j < 4; j++) acc[i][j] = 0.f;

    for (int tile = 0; tile < NTILE; tile++) {
        const int buf = tile & 1;
        if (tile + 1 < NTILE) { CPWAIT(1); } else { CPWAIT(0); }   // own tile-t staging ready
        __syncthreads();                                           // MMA of tile-1 done with bf16 tiles
        const float* stk = (const float*)(smem + P1_STK + buf*16384);
        const float* stv = (const float*)(smem + P1_STV + buf*16384);
#pragma unroll
        for (int j = 0; j < 4; j++) {
            const int u = t + 256*j, row = u >> 4, dq = (u & 15) * 4;
            const float4 kq = *(const float4*)(stk + u*4);
            const float4 vq = *(const float4*)(stv + u*4);
            const float m = msk[tile*64 + row], msc = m * SCALE;
            float f0 = elu_p1(kq.x*ps - mus[dq+0]) * msc;
            float f1 = elu_p1(kq.y*ps - mus[dq+1]) * msc;
            float f2 = elu_p1(kq.z*ps - mus[dq+2]) * msc;
            float f3 = elu_p1(kq.w*ps - mus[dq+3]) * msc;
            uint2 kh = { pk(f0, f1), pk(f2, f3) };
            uint2 kl2 = { pk(f0 - rbf(f0), f1 - rbf(f1)), pk(f2 - rbf(f2), f3 - rbf(f3)) };
            *(uint2*)&khi[row*PAD + dq] = kh;
            *(uint2*)&klo[row*PAD + dq] = kl2;
            float g0 = vq.x * m, g1 = vq.y * m, g2 = vq.z * m, g3 = vq.w * m;
            uint2 vh2 = { pk(g0, g1), pk(g2, g3) };
            uint2 vl2 = { pk(g0 - rbf(g0), g1 - rbf(g1)), pk(g2 - rbf(g2), g3 - rbf(g3)) };
            *(uint2*)&vhi[row*PAD + dq] = vh2;
            *(uint2*)&vlo[row*PAD + dq] = vl2;
        }
        __syncthreads();                                           // bf16 tiles ready; staging consumed
        if (tile + 2 < NTILE) {                                    // refill this staging buffer
            const float* ks = Kb + (tile + 2)*4096;
            const float* vs = Vb + (tile + 2)*4096;
            const uint32_t kd = sb + P1_STK + buf*16384, vd = sb + P1_STV + buf*16384;
#pragma unroll
            for (int j = 0; j < 4; j++) {
                const int u = t + 256*j;
                cp16(kd + u*16, ks + u*4);
                cp16(vd + u*16, vs + u*4);
            }
            CPCOMMIT();
        }

#pragma unroll
        for (int kl = 0; kl < 64; kl += 16) {
            const uint32_t kadd = (uint32_t)(kl * PAD * 2);
            uint32_t ah[4], al[4];
            ldsm4t(skh + kadd + aoff, ah);
            ldsm4t(skl + kadd + aoff, al);
            uint32_t bh0[4], bl0[4], bh1[4], bl1[4];
            ldsm4t(svh + kadd + boff,      bh0);
            ldsm4t(svl + kadd + boff,      bl0);
            ldsm4t(svh + kadd + boff + 32, bh1);
            ldsm4t(svl + kadd + boff + 32, bl1);
            mma16816(acc[0], ah, bh0[0], bh0[1]);
            mma16816(acc[0], ah, bl0[0], bl0[1]);
            mma16816(acc[0], al, bh0[0], bh0[1]);
            mma16816(acc[1], ah, bh0[2], bh0[3]);
            mma16816(acc[1], ah, bl0[2], bl0[3]);
            mma16816(acc[1], al, bh0[2], bh0[3]);
            mma16816(acc[2], ah, bh1[0], bh1[1]);
            mma16816(acc[2], ah, bl1[0], bl1[1]);
            mma16816(acc[2], al, bh1[0], bh1[1]);
            mma16816(acc[3], ah, bh1[2], bh1[3]);
            mma16816(acc[3], ah, bl1[2], bl1[3]);
            mma16816(acc[3], al, bh1[2], bh1[3]);
        }
    }

    float* outp = g_scratch + ((size_t)chunk*BH + bhidx) * 4096;
    const int rw = lane >> 2, cq = (lane & 3) * 2;
#pragma unroll
    for (int j = 0; j < 4; j++) {
        float2 lo = { acc[j][0], acc[j][1] };
        float2 hi = { acc[j][2], acc[j][3] };
        *(float2*)&outp[(md + rw) * 64 + ne + 8*j + cq]     = lo;
        *(float2*)&outp[(md + 8 + rw) * 64 + ne + 8*j + cq] = hi;
    }
}

// ============================================================
// Reduce: KV = sum over chunks; emit bf16 hi/lo. grid (BH, 4), 256 thr.
// ============================================================
__global__ void __launch_bounds__(256)
reduce_kernel() {
    const int bhidx = blockIdx.x, part = blockIdx.y, t = threadIdx.x;
    const int pos = part*1024 + t*4;
    float4 s = make_float4(0.f, 0.f, 0.f, 0.f);
#pragma unroll
    for (int c = 0; c < NCHUNK; c++) {
        const float4 v = *(const float4*)(g_scratch + ((size_t)c*BH + bhidx)*4096 + pos);
        s.x += v.x; s.y += v.y; s.z += v.z; s.w += v.w;
    }
    uint2 hi = { pk(s.x, s.y), pk(s.z, s.w) };
    uint2 lo = { pk(s.x - rbf(s.x), s.y - rbf(s.y)), pk(s.z - rbf(s.z), s.w - rbf(s.w)) };
    *(uint2*)(g_KVhi + (size_t)bhidx*4096 + pos) = hi;
    *(uint2*)(g_KVlo + (size_t)bhidx*4096 + pos) = lo;
}

// ============================================================
// Phase 2: out[l][e] = sum_d Qf[l][d]*KV[d][e]
// grid (Ll/128, BH), 128 thr / 4 warps; 2 x 64-row blocks per CTA,
// both prefetched up-front via cp.async.
// ============================================================
__global__ void __launch_bounds__(128, 3)
phase2_kernel(const float* __restrict__ Qp, float* __restrict__ outp) {
    extern __shared__ char smem[];
    const uint32_t sb = s2u(smem);
    const int t = threadIdx.x, lane = t & 31, w = t >> 5;
    const int rb = blockIdx.x, bhidx = blockIdx.y;

    const float* __restrict__ Qb = Qp + ((size_t)bhidx*Ll + (size_t)rb*128) * 64;

    // prefetch both Q blocks
#pragma unroll
    for (int st = 0; st < 2; st++) {
        const float* qs = Qb + st*4096;
        const uint32_t qd = sb + P2_STQ + st*16384;
#pragma unroll
        for (int j = 0; j < 8; j++) {
            const int u = t + 128*j;
            cp16(qd + u*16, qs + u*4);
        }
        CPCOMMIT();
    }

    // KV tiles (regular loads; L2-resident)
    __nv_bfloat16* kvh = (__nv_bfloat16*)(smem + P2_KVH);
    __nv_bfloat16* kvl = (__nv_bfloat16*)(smem + P2_KVL);
#pragma unroll
    for (int i = 0; i < 4; i++) {
        const int idx8 = t + 128*i;
        const int row = idx8 >> 3, cg = (idx8 & 7) * 8;
        *(uint4*)&kvh[row*PAD + cg] = *(const uint4*)(g_KVhi + (size_t)bhidx*4096 + row*64 + cg);
        *(uint4*)&kvl[row*PAD + cg] = *(const uint4*)(g_KVlo + (size_t)bhidx*4096 + row*64 + cg);
    }

    __nv_bfloat16* qhi = (__nv_bfloat16*)(smem + P2_QHI);
    __nv_bfloat16* qlo = (__nv_bfloat16*)(smem + P2_QLO);
    const int l0 = w * 16;
    const int gr = lane >> 3, r8 = lane & 7;
    const uint32_t aoff = ((uint32_t)((l0 + ((gr & 1) ? 8 : 0) + r8) * PAD + ((gr & 2) ? 8 : 0))) * 2;
    const uint32_t boff = ((uint32_t)((((gr & 1) ? 8 : 0) + r8) * PAD + ((gr & 2) ? 8 : 0))) * 2;
    const uint32_t sqh = sb + P2_QHI, sql = sb + P2_QLO, svh = sb + P2_KVH, svl = sb + P2_KVL;

#pragma unroll
    for (int bt = 0; bt < 2; bt++) {
        if (bt == 0) { CPWAIT(1); } else { CPWAIT(0); }
        __syncthreads();   // bt=0: KV tiles visible; bt=1: prev MMA done with q tiles
        const float* stq = (const float*)(smem + P2_STQ + bt*16384);
#pragma unroll
        for (int j = 0; j < 8; j++) {
            const int u = t + 128*j, row = u >> 4, dq = (u & 15) * 4;
            const float4 q = *(const float4*)(stq + u*4);
            float f0 = elu_p1(q.x) * SCALE, f1 = elu_p1(q.y) * SCALE;
            float f2 = elu_p1(q.z) * SCALE, f3 = elu_p1(q.w) * SCALE;
            uint2 qh = { pk(f0, f1), pk(f2, f3) };
            uint2 ql = { pk(f0 - rbf(f0), f1 - rbf(f1)), pk(f2 - rbf(f2), f3 - rbf(f3)) };
            *(uint2*)&qhi[row*PAD + dq] = qh;
            *(uint2*)&qlo[row*PAD + dq] = ql;
        }
        __syncthreads();

        float acc[8][4];
#pragma unroll
        for (int i = 0; i < 8; i++)
#pragma unroll
            for (int j = 0; j < 4; j++) acc[i][j] = 0.f;

#pragma unroll
        for (int kd = 0; kd < 64; kd += 16) {
            uint32_t ah[4], al[4];
            ldsm4(sqh + aoff + (uint32_t)(kd*2), ah);
            ldsm4(sql + aoff + (uint32_t)(kd*2), al);
#pragma unroll
            for (int p = 0; p < 4; p++) {
                const uint32_t badd = (uint32_t)(kd * PAD * 2 + p * 32);
                uint32_t vh[4], vl[4];
                ldsm4t(svh + badd + boff, vh);
                ldsm4t(svl + badd + boff, vl);
                mma16816(acc[2*p], ah, vh[0], vh[1]);
                mma16816(acc[2*p], ah, vl[0], vl[1]);
                mma16816(acc[2*p], al, vh[0], vh[1]);
                mma16816(acc[2*p+1], ah, vh[2], vh[3]);
                mma16816(acc[2*p+1], ah, vl[2], vl[3]);
                mma16816(acc[2*p+1], al, vh[2], vh[3]);
            }
        }

        float* __restrict__ ob = outp + ((size_t)bhidx*Ll + (size_t)rb*128 + (size_t)bt*64) * 64;
        const int rw = lane >> 2, cq = (lane & 3) * 2;
#pragma unroll
        for (int j = 0; j < 8; j++) {
            float2 lo = { acc[j][0], acc[j][1] };
            float2 hi = { acc[j][2], acc[j][3] };
            *(float2*)&ob[(l0 + rw) * 64 + 8*j + cq]     = lo;
            *(float2*)&ob[(l0 + 8 + rw) * 64 + 8*j + cq] = hi;
        }
    }
}

// ============================================================
// Launch
// ============================================================
extern "C" void kernel_launch(void* const* d_in, const int* in_sizes, int n_in,
                              void* d_out, int out_size) {
    const float* Q    = (const float*)d_in[0];
    const float* K    = (const float*)d_in[1];
    const float* V    = (const float*)d_in[2];
    const float* mask = (const float*)d_in[3];
    const float* pi   = (const float*)d_in[4];
    const float* mu   = (const float*)d_in[5];
    float* out = (float*)d_out;

    cudaFuncSetAttribute(phase1_kernel, cudaFuncAttributeMaxDynamicSharedMemorySize, P1_SZ);
    cudaFuncSetAttribute(phase2_kernel, cudaFuncAttributeMaxDynamicSharedMemorySize, P2_SZ);

    dim3 g1(NCHUNK, BH);
    phase1_kernel<<<g1, 256, P1_SZ>>>(K, V, mask, pi, mu);
    dim3 g2(BH, 4);
    reduce_kernel<<<g2, 256>>>();
    dim3 g3(Ll / 128, BH);
    phase2_kernel<<<g3, 128, P2_SZ>>>(Q, out);
}

// round 8
// speedup vs baseline: 1.5806x; 1.0284x over previous
#include <cuda_runtime.h>
#include <cuda_bf16.h>
#include <cstdint>

#define Bb 4
#define Hh 16
#define Ll 8192
#define Dd 64
#define BH (Bb*Hh)
#define SCALE 0.10511205190671431f   // 8192^(-1/4)
#define NCHUNK 16
#define RPC (Ll/NCHUNK)              // 512 rows per chunk
#define NTILE (RPC/64)               // 8 tiles of 64 rows
#define PAD 72                       // bf16 row stride (144B, conflict-free)

// __device__ scratch (allocation-free rule)
__device__ float g_scratch[(size_t)NCHUNK*BH*Dd*Dd];          // 16.7 MB fp32 partial KV
__device__ __nv_bfloat16 g_KVhi[(size_t)BH*Dd*Dd];            // 0.5 MB
__device__ __nv_bfloat16 g_KVlo[(size_t)BH*Dd*Dd];            // 0.5 MB

// ---------------- helpers ----------------
__device__ __forceinline__ uint32_t s2u(const void* p) {
    uint32_t a;
    asm("{ .reg .u64 t; cvta.to.shared.u64 t, %1; cvt.u32.u64 %0, t; }" : "=r"(a) : "l"(p));
    return a;
}
__device__ __forceinline__ void cp16(uint32_t dst, const void* src) {
    asm volatile("cp.async.cg.shared.global [%0], [%1], 16;" :: "r"(dst), "l"(src) : "memory");
}
#define CPCOMMIT() asm volatile("cp.async.commit_group;" ::: "memory")
#define CPWAIT(n)  asm volatile("cp.async.wait_group %0;" :: "n"(n) : "memory")
__device__ __forceinline__ void ldsm4t(uint32_t addr, uint32_t* r) {
    asm volatile("ldmatrix.sync.aligned.m8n8.x4.trans.shared.b16 {%0,%1,%2,%3}, [%4];"
                 : "=r"(r[0]), "=r"(r[1]), "=r"(r[2]), "=r"(r[3]) : "r"(addr));
}
__device__ __forceinline__ void ldsm4(uint32_t addr, uint32_t* r) {
    asm volatile("ldmatrix.sync.aligned.m8n8.x4.shared.b16 {%0,%1,%2,%3}, [%4];"
                 : "=r"(r[0]), "=r"(r[1]), "=r"(r[2]), "=r"(r[3]) : "r"(addr));
}
__device__ __forceinline__ void mma16816(float* c, const uint32_t* a, uint32_t b0, uint32_t b1) {
    asm volatile("mma.sync.aligned.m16n8k16.row.col.f32.bf16.bf16.f32 "
                 "{%0,%1,%2,%3},{%4,%5,%6,%7},{%8,%9},{%0,%1,%2,%3};"
                 : "+f"(c[0]), "+f"(c[1]), "+f"(c[2]), "+f"(c[3])
                 : "r"(a[0]), "r"(a[1]), "r"(a[2]), "r"(a[3]), "r"(b0), "r"(b1));
}
__device__ __forceinline__ float elu_p1(float x) { float e = __expf(x); return x > 0.0f ? x + 1.0f : e; }
// pack (a -> bits[15:0], b -> bits[31:16])
__device__ __forceinline__ uint32_t cvt2(float a, float b) {
    uint32_t r;
    asm("cvt.rn.bf16x2.f32 %0, %1, %2;" : "=r"(r) : "f"(b), "f"(a));
    return r;
}
__device__ __forceinline__ float bflo(uint32_t u) { return __uint_as_float(u << 16); }
__device__ __forceinline__ float bfhi(uint32_t u) { return __uint_as_float(u & 0xffff0000u); }
// split 4 floats -> hi pair, lo pair (2 cvt + 2 lop + 4 fadd + 2 cvt)
__device__ __forceinline__ void split4(float f0, float f1, float f2, float f3,
                                       uint2& hi, uint2& lo) {
    hi.x = cvt2(f0, f1);  hi.y = cvt2(f2, f3);
    lo.x = cvt2(f0 - bflo(hi.x), f1 - bfhi(hi.x));
    lo.y = cvt2(f2 - bflo(hi.y), f3 - bfhi(hi.y));
}

// phase1 dynamic smem: two bf16 tile buffers + mus
#define T_KHI 0
#define T_KLO 9216
#define T_VHI 18432
#define T_VLO 27648
#define BUFSZ 36864
#define P1_MUS (2*BUFSZ)
#define P1_SZ  (2*BUFSZ + 256)
// phase2 dynamic smem layout
#define P2_STQ 0            // 2 x 16384 fp32 staging Q
#define P2_QHI 32768
#define P2_QLO 41984
#define P2_KVH 51200
#define P2_KVL 60416
#define P2_SZ  69632

// ============================================================
// Phase 1: partial KV[d][e] = sum_l Kf[l][d]*Vm[l][e]
// grid (NCHUNK, BH), 256 thr / 8 warps.
// Register-prefetched loads + double-buffered bf16 tiles, 1 sync/tile:
//   per tile: LDG(t+1) -> MMA(t) -> transform(t+1) -> sync
// ============================================================
__global__ void __launch_bounds__(256, 2)
phase1_kernel(const float* __restrict__ Kp, const float* __restrict__ Vp,
              const float* __restrict__ maskp, const float* __restrict__ pip,
              const float* __restrict__ mup) {
    extern __shared__ char smem[];
    const uint32_t sb = s2u(smem);
    float* mus = (float*)(smem + P1_MUS);
    const int t = threadIdx.x, lane = t & 31, w = t >> 5;
    const int chunk = blockIdx.x, bhidx = blockIdx.y, b = bhidx / Hh, h = bhidx % Hh;

    const float p0 = fminf(fmaxf(pip[0], 0.f), 1.f);
    const float p1 = fminf(fmaxf(pip[1], 0.f), 1.f);
    const float ps = p0 + p1;
    if (t < 64) mus[t] = p0 * mup[h*64 + t] + p1 * mup[(Hh + h)*64 + t];

    const size_t base = ((size_t)bhidx*Ll + (size_t)chunk*RPC) * 64;
    const float* __restrict__ Kb = Kp + base;
    const float* __restrict__ Vb = Vp + base;
    const float* __restrict__ mb = maskp + (size_t)b*Ll + (size_t)chunk*RPC;

    const int md = (w & 3) * 16, ne = (w >> 2) * 32;
    const int gr = lane >> 3, r8 = lane & 7;
    const uint32_t aoff = ((uint32_t)((((gr & 2) ? 8 : 0) + r8) * PAD + md + ((gr & 1) ? 8 : 0))) * 2;
    const uint32_t boff = ((uint32_t)((((gr & 1) ? 8 : 0) + r8) * PAD + ne + ((gr & 2) ? 8 : 0))) * 2;

    float acc[4][4];
#pragma unroll
    for (int i = 0; i < 4; i++)
#pragma unroll
        for (int j = 0; j < 4; j++) acc[i][j] = 0.f;

    float4 kreg[4], vreg[4];
    float  mreg[4];
    const int trow = t >> 4, tdq = (t & 15) * 4;   // this thread's row/col group

#define LOAD_TILE(tl) do { const int _l0 = (tl) * 64; \
    _Pragma("unroll") \
    for (int j = 0; j < 4; j++) { \
        const size_t off = (size_t)(_l0 + trow + 16*j)*64 + tdq; \
        kreg[j] = *(const float4*)(Kb + off); \
        vreg[j] = *(const float4*)(Vb + off); \
        mreg[j] = mb[_l0 + trow + 16*j]; \
    } } while (0)

#define TRANSFORM(bufbase) do { \
    char* _bp = smem + (bufbase); \
    __nv_bfloat16* _khi = (__nv_bfloat16*)(_bp + T_KHI); \
    __nv_bfloat16* _klo = (__nv_bfloat16*)(_bp + T_KLO); \
    __nv_bfloat16* _vhi = (__nv_bfloat16*)(_bp + T_VHI); \
    __nv_bfloat16* _vlo = (__nv_bfloat16*)(_bp + T_VLO); \
    _Pragma("unroll") \
    for (int j = 0; j < 4; j++) { \
        const int row = trow + 16*j; \
        const float m = mreg[j], msc = m * SCALE; \
        float f0 = elu_p1(kreg[j].x*ps - mus[tdq+0]) * msc; \
        float f1 = elu_p1(kreg[j].y*ps - mus[tdq+1]) * msc; \
        float f2 = elu_p1(kreg[j].z*ps - mus[tdq+2]) * msc; \
        float f3 = elu_p1(kreg[j].w*ps - mus[tdq+3]) * msc; \
        uint2 kh, kl; split4(f0, f1, f2, f3, kh, kl); \
        *(uint2*)&_khi[row*PAD + tdq] = kh; \
        *(uint2*)&_klo[row*PAD + tdq] = kl; \
        float g0 = vreg[j].x * m, g1 = vreg[j].y * m; \
        float g2 = vreg[j].z * m, g3 = vreg[j].w * m; \
        uint2 vh, vl; split4(g0, g1, g2, g3, vh, vl); \
        *(uint2*)&_vhi[row*PAD + tdq] = vh; \
        *(uint2*)&_vlo[row*PAD + tdq] = vl; \
    } } while (0)

    LOAD_TILE(0);
    __syncthreads();          // mus[] visible to ALL threads before TRANSFORM reads it
    TRANSFORM(0);
    __syncthreads();

    for (int tile = 0; tile < NTILE; tile++) {
        const uint32_t bufb = (uint32_t)((tile & 1) * BUFSZ);
        if (tile + 1 < NTILE) LOAD_TILE(tile + 1);   // LDGs in flight under MMA

        const uint32_t skh = sb + bufb + T_KHI, skl = sb + bufb + T_KLO;
        const uint32_t svh = sb + bufb + T_VHI, svl = sb + bufb + T_VLO;
#pragma unroll
        for (int kl = 0; kl < 64; kl += 16) {
            const uint32_t kadd = (uint32_t)(kl * PAD * 2);
            uint32_t ah[4], al[4];
            ldsm4t(skh + kadd + aoff, ah);
            ldsm4t(skl + kadd + aoff, al);
            uint32_t bh0[4], bl0[4], bh1[4], bl1[4];
            ldsm4t(svh + kadd + boff,      bh0);
            ldsm4t(svl + kadd + boff,      bl0);
            ldsm4t(svh + kadd + boff + 32, bh1);
            ldsm4t(svl + kadd + boff + 32, bl1);
            mma16816(acc[0], ah, bh0[0], bh0[1]);
            mma16816(acc[0], ah, bl0[0], bl0[1]);
            mma16816(acc[0], al, bh0[0], bh0[1]);
            mma16816(acc[1], ah, bh0[2], bh0[3]);
            mma16816(acc[1], ah, bl0[2], bl0[3]);
            mma16816(acc[1], al, bh0[2], bh0[3]);
            mma16816(acc[2], ah, bh1[0], bh1[1]);
            mma16816(acc[2], ah, bl1[0], bl1[1]);
            mma16816(acc[2], al, bh1[0], bh1[1]);
            mma16816(acc[3], ah, bh1[2], bh1[3]);
            mma16816(acc[3], ah, bl1[2], bl1[3]);
            mma16816(acc[3], al, bh1[2], bh1[3]);
        }
        if (tile + 1 < NTILE) TRANSFORM((uint32_t)(((tile + 1) & 1) * BUFSZ));
        __syncthreads();
    }
#undef LOAD_TILE
#undef TRANSFORM

    float* outp = g_scratch + ((size_t)chunk*BH + bhidx) * 4096;
    const int rw = lane >> 2, cq = (lane & 3) * 2;
#pragma unroll
    for (int j = 0; j < 4; j++) {
        float2 lo = { acc[j][0], acc[j][1] };
        float2 hi = { acc[j][2], acc[j][3] };
        *(float2*)&outp[(md + rw) * 64 + ne + 8*j + cq]     = lo;
        *(float2*)&outp[(md + 8 + rw) * 64 + ne + 8*j + cq] = hi;
    }
}

// ============================================================
// Reduce: KV = sum over chunks; emit bf16 hi/lo. grid (BH, 4), 256 thr.
// ============================================================
__global__ void __launch_bounds__(256)
reduce_kernel() {
    const int bhidx = blockIdx.x, part = blockIdx.y, t = threadIdx.x;
    const int pos = part*1024 + t*4;
    float4 s = make_float4(0.f, 0.f, 0.f, 0.f);
#pragma unroll
    for (int c = 0; c < NCHUNK; c++) {
        const float4 v = *(const float4*)(g_scratch + ((size_t)c*BH + bhidx)*4096 + pos);
        s.x += v.x; s.y += v.y; s.z += v.z; s.w += v.w;
    }
    uint2 hi, lo;
    split4(s.x, s.y, s.z, s.w, hi, lo);
    *(uint2*)(g_KVhi + (size_t)bhidx*4096 + pos) = hi;
    *(uint2*)(g_KVlo + (size_t)bhidx*4096 + pos) = lo;
}

// ============================================================
// Phase 2: out[l][e] = sum_d Qf[l][d]*KV[d][e]
// grid (Ll/128, BH), 128 thr / 4 warps; 2 x 64-row blocks per CTA,
// both prefetched up-front via cp.async. 3 CTAs/SM.
// ============================================================
__global__ void __launch_bounds__(128, 3)
phase2_kernel(const float* __restrict__ Qp, float* __restrict__ outp) {
    extern __shared__ char smem[];
    const uint32_t sb = s2u(smem);
    const int t = threadIdx.x, lane = t & 31, w = t >> 5;
    const int rb = blockIdx.x, bhidx = blockIdx.y;

    const float* __restrict__ Qb = Qp + ((size_t)bhidx*Ll + (size_t)rb*128) * 64;

    // prefetch both Q blocks
#pragma unroll
    for (int st = 0; st < 2; st++) {
        const float* qs = Qb + st*4096;
        const uint32_t qd = sb + P2_STQ + st*16384;
#pragma unroll
        for (int j = 0; j < 8; j++) {
            const int u = t + 128*j;
            cp16(qd + u*16, qs + u*4);
        }
        CPCOMMIT();
    }

    // KV tiles (regular loads; L2-resident)
    __nv_bfloat16* kvh = (__nv_bfloat16*)(smem + P2_KVH);
    __nv_bfloat16* kvl = (__nv_bfloat16*)(smem + P2_KVL);
#pragma unroll
    for (int i = 0; i < 4; i++) {
        const int idx8 = t + 128*i;
        const int row = idx8 >> 3, cg = (idx8 & 7) * 8;
        *(uint4*)&kvh[row*PAD + cg] = *(const uint4*)(g_KVhi + (size_t)bhidx*4096 + row*64 + cg);
        *(uint4*)&kvl[row*PAD + cg] = *(const uint4*)(g_KVlo + (size_t)bhidx*4096 + row*64 + cg);
    }

    __nv_bfloat16* qhi = (__nv_bfloat16*)(smem + P2_QHI);
    __nv_bfloat16* qlo = (__nv_bfloat16*)(smem + P2_QLO);
    const int l0 = w * 16;
    const int gr = lane >> 3, r8 = lane & 7;
    const uint32_t aoff = ((uint32_t)((l0 + ((gr & 1) ? 8 : 0) + r8) * PAD + ((gr & 2) ? 8 : 0))) * 2;
    const uint32_t boff = ((uint32_t)((((gr & 1) ? 8 : 0) + r8) * PAD + ((gr & 2) ? 8 : 0))) * 2;
    const uint32_t sqh = sb + P2_QHI, sql = sb + P2_QLO, svh = sb + P2_KVH, svl = sb + P2_KVL;

#pragma unroll
    for (int bt = 0; bt < 2; bt++) {
        if (bt == 0) { CPWAIT(1); } else { CPWAIT(0); }
        __syncthreads();   // bt=0: KV tiles visible; bt=1: prev MMA done with q tiles
        const float* stq = (const float*)(smem + P2_STQ + bt*16384);
#pragma unroll
        for (int j = 0; j < 8; j++) {
            const int u = t + 128*j, row = u >> 4, dq = (u & 15) * 4;
            const float4 q = *(const float4*)(stq + u*4);
            float f0 = elu_p1(q.x) * SCALE, f1 = elu_p1(q.y) * SCALE;
            float f2 = elu_p1(q.z) * SCALE, f3 = elu_p1(q.w) * SCALE;
            uint2 qh, ql;
            split4(f0, f1, f2, f3, qh, ql);
            *(uint2*)&qhi[row*PAD + dq] = qh;
            *(uint2*)&qlo[row*PAD + dq] = ql;
        }
        __syncthreads();

        float acc[8][4];
#pragma unroll
        for (int i = 0; i < 8; i++)
#pragma unroll
            for (int j = 0; j < 4; j++) acc[i][j] = 0.f;

#pragma unroll
        for (int kd = 0; kd < 64; kd += 16) {
            uint32_t ah[4], al[4];
            ldsm4(sqh + aoff + (uint32_t)(kd*2), ah);
            ldsm4(sql + aoff + (uint32_t)(kd*2), al);
#pragma unroll
            for (int p = 0; p < 4; p++) {
                const uint32_t badd = (uint32_t)(kd * PAD * 2 + p * 32);
                uint32_t vh[4], vl[4];
                ldsm4t(svh + badd + boff, vh);
                ldsm4t(svl + badd + boff, vl);
                mma16816(acc[2*p], ah, vh[0], vh[1]);
                mma16816(acc[2*p], ah, vl[0], vl[1]);
                mma16816(acc[2*p], al, vh[0], vh[1]);
                mma16816(acc[2*p+1], ah, vh[2], vh[3]);
                mma16816(acc[2*p+1], ah, vl[2], vl[3]);
                mma16816(acc[2*p+1], al, vh[2], vh[3]);
            }
        }

        float* __restrict__ ob = outp + ((size_t)bhidx*Ll + (size_t)rb*128 + (size_t)bt*64) * 64;
        const int rw = lane >> 2, cq = (lane & 3) * 2;
#pragma unroll
        for (int j = 0; j < 8; j++) {
            float2 lo = { acc[j][0], acc[j][1] };
            float2 hi = { acc[j][2], acc[j][3] };
            *(float2*)&ob[(l0 + rw) * 64 + 8*j + cq]     = lo;
            *(float2*)&ob[(l0 + 8 + rw) * 64 + 8*j + cq] = hi;
        }
    }
}

// ============================================================
// Launch
// ============================================================
extern "C" void kernel_launch(void* const* d_in, const int* in_sizes, int n_in,
                              void* d_out, int out_size) {
    const float* Q    = (const float*)d_in[0];
    const float* K    = (const float*)d_in[1];
    const float* V    = (const float*)d_in[2];
    const float* mask = (const float*)d_in[3];
    const float* pi   = (const float*)d_in[4];
    const float* mu   = (const float*)d_in[5];
    float* out = (float*)d_out;

    cudaFuncSetAttribute(phase1_kernel, cudaFuncAttributeMaxDynamicSharedMemorySize, P1_SZ);
    cudaFuncSetAttribute(phase2_kernel, cudaFuncAttributeMaxDynamicSharedMemorySize, P2_SZ);

    dim3 g1(NCHUNK, BH);
    phase1_kernel<<<g1, 256, P1_SZ>>>(K, V, mask, pi, mu);
    dim3 g2(BH, 4);
    reduce_kernel<<<g2, 256>>>();
    dim3 g3(Ll / 128, BH);
    phase2_kernel<<<g3, 128, P2_SZ>>>(Q, out);
}